// round 1
// baseline (speedup 1.0000x reference)
#include <cuda_runtime.h>
#include <math.h>

// Problem constants (fixed by the reference setup)
#define IN_DIM     768
#define DIM        512
#define NUM_BINS   16
#define DAY_LENGTH 64
#define SEQ_N      2048

// Tiling
#define BM 128
#define BF 64
#define BK 16
#define TM 8
#define TF 4
#define NTHREADS 256

// Padded smem strides (floats). Both are multiples of 4 (16B-aligned rows for
// float4 LDS) and not multiples of 32 in the low bits that matter, so the
// transposed stores don't fully serialize on banks.
#define AS_STRIDE 136
#define WS_STRIDE 72

__global__ __launch_bounds__(NTHREADS)
void atom_fused_kernel(const float* __restrict__ x,       // [M, IN_DIM]
                       const float* __restrict__ freqs,   // [DIM, IN_DIM]
                       const float* __restrict__ phase,   // [DIM, 1]
                       const float* __restrict__ heights, // [DIM, NUM_BINS]
                       const float* __restrict__ bias,    // [DIM]
                       const int*   __restrict__ offset_p,// scalar
                       float*       __restrict__ out,     // [M, DIM]
                       int M)
{
    __shared__ float  As[BK][AS_STRIDE];
    __shared__ float  Ws[BK][WS_STRIDE];
    __shared__ float2 Stab[NUM_BINS][BF];   // (S1 prefix, S2 prefix) per local f
    __shared__ float  sm_phase[BF];
    __shared__ float  sm_bias[BF];

    const int tid = threadIdx.x;
    const int tx  = tid & 15;          // f direction, 16 threads * TF(4) = 64
    const int ty  = tid >> 4;          // m direction, 16 threads * TM(8) = 128
    const int f0  = blockIdx.x * BF;
    const int m0  = blockIdx.y * BM;

    // ---- Build spline prefix tables + cache phase/bias (cheap, once per CTA) ----
    // val(u) = sum_{k<=j} (u - k/15) * w_k  with j = floor(15u)
    //        = u * S1[j] - S2[j],  S1[j] = sum_{k<=j} w_k, S2[j] = sum_{k<=j} (k/15) w_k
    if (tid < BF) {
        const int f = f0 + tid;
        float s1 = 0.0f, s2 = 0.0f;
        #pragma unroll
        for (int k = 0; k < NUM_BINS; k++) {
            float h = heights[f * NUM_BINS + k];
            // softplus, overflow-safe
            float w = (h > 20.0f) ? h : log1pf(expf(h));
            s1 += w;
            s2 += ((float)k * (1.0f / 15.0f)) * w;
            Stab[k][tid] = make_float2(s1, s2);
        }
        sm_phase[tid] = phase[f];
        sm_bias[tid]  = bias[f];
    }
    // (ordering vs. epilogue is guaranteed by the __syncthreads inside the loop)

    const float* Atile = x     + (size_t)m0 * IN_DIM;
    const float* Wtile = freqs + (size_t)f0 * IN_DIM;

    float acc[TM][TF];
    #pragma unroll
    for (int i = 0; i < TM; i++)
        #pragma unroll
        for (int j = 0; j < TF; j++) acc[i][j] = 0.0f;

    // ---- Main GEMM loop ----
    for (int k0 = 0; k0 < IN_DIM; k0 += BK) {
        // Load A tile: 128 rows x 16 cols = 512 float4 loads, 2 per thread.
        #pragma unroll
        for (int t = 0; t < 2; t++) {
            int li = tid + t * NTHREADS;
            int r  = li >> 2;
            int c4 = li & 3;
            float4 v = *reinterpret_cast<const float4*>(
                Atile + (size_t)r * IN_DIM + k0 + c4 * 4);
            As[c4 * 4 + 0][r] = v.x;
            As[c4 * 4 + 1][r] = v.y;
            As[c4 * 4 + 2][r] = v.z;
            As[c4 * 4 + 3][r] = v.w;
        }
        // Load W tile: 64 rows x 16 cols = 256 float4 loads, 1 per thread.
        {
            int r  = tid >> 2;
            int c4 = tid & 3;
            float4 v = *reinterpret_cast<const float4*>(
                Wtile + (size_t)r * IN_DIM + k0 + c4 * 4);
            Ws[c4 * 4 + 0][r] = v.x;
            Ws[c4 * 4 + 1][r] = v.y;
            Ws[c4 * 4 + 2][r] = v.z;
            Ws[c4 * 4 + 3][r] = v.w;
        }
        __syncthreads();

        #pragma unroll
        for (int k = 0; k < BK; k++) {
            float4 a0 = *reinterpret_cast<const float4*>(&As[k][ty * TM]);
            float4 a1 = *reinterpret_cast<const float4*>(&As[k][ty * TM + 4]);
            float4 bb = *reinterpret_cast<const float4*>(&Ws[k][tx * TF]);
            float a[TM] = {a0.x, a0.y, a0.z, a0.w, a1.x, a1.y, a1.z, a1.w};
            float b[TF] = {bb.x, bb.y, bb.z, bb.w};
            #pragma unroll
            for (int i = 0; i < TM; i++)
                #pragma unroll
                for (int j = 0; j < TF; j++)
                    acc[i][j] = fmaf(a[i], b[j], acc[i][j]);
        }
        __syncthreads();
    }

    // ---- Fused epilogue: sin -> sigmoid -> spline -> bias -> RoPE ----
    const int offset = *offset_p;
    const int mbase  = m0 + ty * TM;
    const int fbase  = f0 + tx * TF;

    // RoPE inverse frequencies for this thread's two (even,odd) pairs.
    float inv_h[2], inv_d[2];
    #pragma unroll
    for (int p = 0; p < 2; p++) {
        float halfv = (float)(fbase + 2 * p) / (float)DIM;
        inv_h[p] = exp2f(-13.287712379549449f * halfv);  // 10000^-half
        inv_d[p] = exp2f(-16.609640474436812f * halfv);  // 100000^-half
    }

    #pragma unroll
    for (int i = 0; i < TM; i++) {
        const int m = mbase + i;
        const int n = m & (SEQ_N - 1);
        // Float semantics to match the reference exactly (works for any offset).
        float tf    = (float)(n + offset);
        float days  = floorf(tf * (1.0f / (float)DAY_LENGTH));
        float hours = tf - days * (float)DAY_LENGTH;

        float v[TF];
        #pragma unroll
        for (int j = 0; j < TF; j++) {
            const int fl = tx * TF + j;
            float basis = acc[i][j] + sm_phase[fl];
            float s     = sinf(basis);
            float u     = 1.0f / (1.0f + expf(-s));
            int   bin   = (int)(u * 15.0f);
            bin = bin < 0 ? 0 : (bin > 15 ? 15 : bin);
            float2 S = Stab[bin][fl];
            v[j] = fmaf(u, S.x, -S.y) + sm_bias[fl];
        }

        float4 o;
        {
            float sn, cs;
            float ang = fmaf(hours, inv_h[0], days * inv_d[0]);
            sincosf(ang, &sn, &cs);
            o.x = v[0] * cs - v[1] * sn;
            o.y = v[0] * sn + v[1] * cs;
            ang = fmaf(hours, inv_h[1], days * inv_d[1]);
            sincosf(ang, &sn, &cs);
            o.z = v[2] * cs - v[3] * sn;
            o.w = v[2] * sn + v[3] * cs;
        }
        *reinterpret_cast<float4*>(out + (size_t)m * DIM + fbase) = o;
    }
}

extern "C" void kernel_launch(void* const* d_in, const int* in_sizes, int n_in,
                              void* d_out, int out_size)
{
    const float* x       = (const float*)d_in[0];
    const float* freqs   = (const float*)d_in[1];
    const float* phase   = (const float*)d_in[2];
    const float* heights = (const float*)d_in[3];
    const float* bias    = (const float*)d_in[4];
    const int*   offset  = (const int*)d_in[5];
    float*       out     = (float*)d_out;

    const int M = in_sizes[0] / IN_DIM;   // B*N = 16384

    dim3 grid(DIM / BF, M / BM);          // (8, 128)
    atom_fused_kernel<<<grid, NTHREADS>>>(x, freqs, phase, heights, bias,
                                          offset, out, M);
}

// round 5
// speedup vs baseline: 3.0856x; 3.0856x over previous
#include <cuda_runtime.h>
#include <math.h>
#include <stdint.h>

// ---------------- problem constants ----------------
#define IN_DIM     768
#define DIM        512
#define NUM_BINS   16
#define SEQ_N      2048
#define DAY_LENGTH 64

// ---------------- tiling ----------------
#define BM       128
#define BN       256
#define BK       32
#define STAGES   3
#define NTHREADS 256
#define KTILES   (IN_DIM / BK)        // 24

// warp tiling: 8 warps, 2 (M) x 4 (N), each 64x64
#define MT 4                          // 4 x m16
#define NT 8                          // 8 x n8

// padded smem strides (floats): stride 36 -> fragment LDS banks = 4r+c (conflict-free)
#define AS_STRIDE 36
#define BS_STRIDE 36
#define A_STAGE_FLOATS (BM * AS_STRIDE)              // 4608
#define B_STAGE_FLOATS (BN * BS_STRIDE)              // 9216
#define STAGE_FLOATS   (A_STAGE_FLOATS + B_STAGE_FLOATS)
#define SMEM_BYTES     (STAGES * STAGE_FLOATS * 4)   // 165888

__device__ __forceinline__ uint32_t smem_u32(const void* p) {
    uint32_t a;
    asm("{ .reg .u64 t; cvta.to.shared.u64 t, %1; cvt.u32.u64 %0, t; }" : "=r"(a) : "l"(p));
    return a;
}
__device__ __forceinline__ void cp16(uint32_t dst, const void* src) {
    asm volatile("cp.async.cg.shared.global [%0], [%1], 16;" :: "r"(dst), "l"(src) : "memory");
}

__device__ __forceinline__ void mma_tf32(float* c, const uint32_t* a, const uint32_t* b) {
    asm volatile(
        "mma.sync.aligned.m16n8k8.row.col.f32.tf32.tf32.f32 "
        "{%0,%1,%2,%3}, {%4,%5,%6,%7}, {%8,%9}, {%0,%1,%2,%3};"
        : "+f"(c[0]), "+f"(c[1]), "+f"(c[2]), "+f"(c[3])
        : "r"(a[0]), "r"(a[1]), "r"(a[2]), "r"(a[3]), "r"(b[0]), "r"(b[1]));
}

// ---------------- kernel ----------------
__global__ __launch_bounds__(NTHREADS, 1)
void atom_mma_kernel(const float* __restrict__ x,        // [M, IN_DIM]
                     const float* __restrict__ freqs,    // [DIM, IN_DIM]
                     const float* __restrict__ phase,    // [DIM]
                     const float* __restrict__ heights,  // [DIM, NUM_BINS]
                     const float* __restrict__ bias,     // [DIM]
                     const int*   __restrict__ offset_p,
                     float*       __restrict__ out)      // [M, DIM]
{
    extern __shared__ float smem[];
    const uint32_t sbase = smem_u32(smem);
    const int tid  = threadIdx.x;
    const int wid  = tid >> 5;
    const int lane = tid & 31;
    const int wm   = wid & 1;          // warp M index (0..1)
    const int wn   = wid >> 1;         // warp N index (0..3)
    const int f0   = blockIdx.x * BN;
    const int m0   = blockIdx.y * BM;

    const int lr = lane >> 2;          // 0..7
    const int lc = lane & 3;           // 0..3

    float acc[MT][NT][4];
    #pragma unroll
    for (int i = 0; i < MT; i++)
        #pragma unroll
        for (int j = 0; j < NT; j++)
            #pragma unroll
            for (int q = 0; q < 4; q++) acc[i][j][q] = 0.0f;

    // ---- async stage loader ----
    auto load_stage = [&](int s, int kc) {
        const uint32_t abase = sbase + (uint32_t)s * (STAGE_FLOATS * 4);
        const float* ag = x + (size_t)m0 * IN_DIM + kc * BK;
        #pragma unroll
        for (int j = 0; j < 4; j++) {          // A: 128 rows x 8 16B-chunks
            int idx = tid + j * NTHREADS;
            int row = idx >> 3, c4 = idx & 7;
            cp16(abase + row * (AS_STRIDE * 4) + c4 * 16,
                 ag + (size_t)row * IN_DIM + c4 * 4);
        }
        const uint32_t bbase = abase + A_STAGE_FLOATS * 4;
        const float* bg = freqs + (size_t)f0 * IN_DIM + kc * BK;
        #pragma unroll
        for (int j = 0; j < 8; j++) {          // B: 256 rows x 8 16B-chunks
            int idx = tid + j * NTHREADS;
            int row = idx >> 3, c4 = idx & 7;
            cp16(bbase + row * (BS_STRIDE * 4) + c4 * 16,
                 bg + (size_t)row * IN_DIM + c4 * 4);
        }
        asm volatile("cp.async.commit_group;" ::: "memory");
    };

    // prologue: stages 0,1
    load_stage(0, 0);
    load_stage(1, 1);

    for (int kc = 0; kc < KTILES; kc++) {
        if (kc < KTILES - 1) asm volatile("cp.async.wait_group 1;" ::: "memory");
        else                 asm volatile("cp.async.wait_group 0;" ::: "memory");
        __syncthreads();
        if (kc + 2 < KTILES) load_stage((kc + 2) % STAGES, kc + 2);

        const float* sa = smem + (kc % STAGES) * STAGE_FLOATS;
        const float* sb = sa + A_STAGE_FLOATS;

        #pragma unroll
        for (int kk = 0; kk < 4; kk++) {       // 4 k8-steps per BK=32
            const int kb = kk * 8;
            uint32_t afrag[MT][4], bfrag[NT][2];
            #pragma unroll
            for (int mt = 0; mt < MT; mt++) {
                int r0 = wm * 64 + mt * 16 + lr;
                afrag[mt][0] = __float_as_uint(sa[r0 * AS_STRIDE + kb + lc]);
                afrag[mt][1] = __float_as_uint(sa[(r0 + 8) * AS_STRIDE + kb + lc]);
                afrag[mt][2] = __float_as_uint(sa[r0 * AS_STRIDE + kb + lc + 4]);
                afrag[mt][3] = __float_as_uint(sa[(r0 + 8) * AS_STRIDE + kb + lc + 4]);
            }
            #pragma unroll
            for (int nt = 0; nt < NT; nt++) {
                int c0 = wn * 64 + nt * 8 + lr;
                bfrag[nt][0] = __float_as_uint(sb[c0 * BS_STRIDE + kb + lc]);
                bfrag[nt][1] = __float_as_uint(sb[c0 * BS_STRIDE + kb + lc + 4]);
            }
            #pragma unroll
            for (int mt = 0; mt < MT; mt++)
                #pragma unroll
                for (int nt = 0; nt < NT; nt++)
                    mma_tf32(acc[mt][nt], afrag[mt], bfrag[nt]);
        }
    }
    __syncthreads();

    // ---- build epilogue tables into freed smem ----
    // val(u) = u*S1[bin] - S2[bin] + bias, prefix sums of softplus(heights)
    float2* stab = reinterpret_cast<float2*>(smem);        // [BN][NUM_BINS]
    float*  ptab = smem + BN * NUM_BINS * 2;               // [BN]
    float*  btab = ptab + BN;                              // [BN]
    {
        int fg = f0 + tid;                                 // one f per thread
        float s1 = 0.0f, s2 = 0.0f;
        float2* row = stab + tid * NUM_BINS;
        #pragma unroll
        for (int k = 0; k < NUM_BINS; k++) {
            float h  = heights[fg * NUM_BINS + k];
            float wv = (h > 20.0f) ? h : log1pf(expf(h));  // softplus (accurate)
            s1 += wv;
            s2 += (float)k * (1.0f / 15.0f) * wv;
            row[k] = make_float2(s1, s2);
        }
        ptab[tid] = phase[fg];
        btab[tid] = bias[fg];
    }
    __syncthreads();

    // ---- fused epilogue: sin -> sigmoid -> spline -> bias -> RoPE ----
    const int offset = *offset_p;

    // per-thread RoPE inverse freqs for the 8 nt column-pairs
    float invh[NT], invd[NT];
    #pragma unroll
    for (int nt = 0; nt < NT; nt++) {
        int fe = f0 + wn * 64 + nt * 8 + lc * 2;           // even global f
        float hv = (float)fe * (1.0f / (float)DIM);
        invh[nt] = exp2f(-13.287712379549449f * hv);       // 10000^-half
        invd[nt] = exp2f(-16.609640474436812f * hv);       // 100000^-half
    }

    #pragma unroll
    for (int mt = 0; mt < MT; mt++) {
        #pragma unroll
        for (int o = 0; o < 2; o++) {
            const int m = m0 + wm * 64 + mt * 16 + o * 8 + lr;
            const int nseq  = m & (SEQ_N - 1);
            const float tf0 = (float)(nseq + offset);
            const float days  = floorf(tf0 * (1.0f / (float)DAY_LENGTH));
            const float hours = tf0 - days * (float)DAY_LENGTH;

            #pragma unroll
            for (int nt = 0; nt < NT; nt++) {
                const int fl = wn * 64 + nt * 8 + lc * 2;  // even local f
                float vv[2];
                #pragma unroll
                for (int e = 0; e < 2; e++) {
                    float basis = acc[mt][nt][o * 2 + e] + ptab[fl + e];
                    float s = __sinf(basis);
                    float u = __fdividef(1.0f, 1.0f + __expf(-s));
                    int bin = (int)(u * 15.0f);
                    bin = bin < 0 ? 0 : (bin > 15 ? 15 : bin);
                    float2 S = stab[(fl + e) * NUM_BINS + bin];
                    vv[e] = fmaf(u, S.x, -S.y) + btab[fl + e];
                }
                float sn, cs;
                __sincosf(fmaf(hours, invh[nt], days * invd[nt]), &sn, &cs);
                float2 o2;
                o2.x = vv[0] * cs - vv[1] * sn;
                o2.y = vv[0] * sn + vv[1] * cs;
                *reinterpret_cast<float2*>(out + (size_t)m * DIM + f0 + fl) = o2;
            }
        }
    }
}

// ---------------- launch ----------------
extern "C" void kernel_launch(void* const* d_in, const int* in_sizes, int n_in,
                              void* d_out, int out_size)
{
    const float* x       = (const float*)d_in[0];
    const float* freqs   = (const float*)d_in[1];
    const float* phase   = (const float*)d_in[2];
    const float* heights = (const float*)d_in[3];
    const float* bias    = (const float*)d_in[4];
    const int*   offset  = (const int*)d_in[5];
    float*       out     = (float*)d_out;

    const int M = in_sizes[0] / IN_DIM;              // 16384

    // Unconditional (stateless — no static guards per harness rules).
    // Not a stream op, so it is graph-capture safe and idempotent.
    cudaFuncSetAttribute(atom_mma_kernel,
                         cudaFuncAttributeMaxDynamicSharedMemorySize, SMEM_BYTES);

    dim3 grid(DIM / BN, M / BM);                     // (2, 128)
    atom_mma_kernel<<<grid, NTHREADS, SMEM_BYTES>>>(x, freqs, phase, heights, bias,
                                                    offset, out);
}